// round 15
// baseline (speedup 1.0000x reference)
#include <cuda_runtime.h>
#include <cuda_fp16.h>
#include <cstdint>

#define B_ 64
#define N_ 1024
#define F_ 128
#define H_ 256

// Scratch (allocation-free rule: __device__ globals)
__device__ __half g_adj16[(size_t)B_ * N_ * N_];
__device__ __half g_embs16[B_ * N_ * F_];
__device__ __half g_W016[F_ * H_];
__device__ __half g_W116[H_ * H_];
__device__ __half g_T1h[B_ * N_ * F_];
__device__ __half g_hid1h[(size_t)B_ * N_ * H_];
__device__ __half g_T2h[(size_t)B_ * N_ * H_];
__device__ float g_part[B_ * 8 * H_];

__device__ __forceinline__ uint32_t s2u(const void* p) {
    uint32_t a;
    asm("{ .reg .u64 t; cvta.to.shared.u64 t, %1; cvt.u32.u64 %0, t; }" : "=r"(a) : "l"(p));
    return a;
}
__device__ __forceinline__ uint32_t pack2(float a, float b) {
    __half2 h = __floats2half2_rn(a, b);
    return *(uint32_t*)&h;
}
__device__ __forceinline__ void ldsm4(uint32_t* r, uint32_t addr) {
    asm volatile("ldmatrix.sync.aligned.m8n8.x4.shared.b16 {%0,%1,%2,%3}, [%4];"
                 : "=r"(r[0]), "=r"(r[1]), "=r"(r[2]), "=r"(r[3]) : "r"(addr));
}
__device__ __forceinline__ void ldsm4t(uint32_t* r, uint32_t addr) {
    asm volatile("ldmatrix.sync.aligned.m8n8.x4.trans.shared.b16 {%0,%1,%2,%3}, [%4];"
                 : "=r"(r[0]), "=r"(r[1]), "=r"(r[2]), "=r"(r[3]) : "r"(addr));
}
__device__ __forceinline__ void mma_h(float* d, const uint32_t* a, const uint32_t* b) {
    asm volatile(
        "mma.sync.aligned.m16n8k16.row.col.f32.f16.f16.f32 "
        "{%0,%1,%2,%3}, {%4,%5,%6,%7}, {%8,%9}, {%0,%1,%2,%3};"
        : "+f"(d[0]), "+f"(d[1]), "+f"(d[2]), "+f"(d[3])
        : "r"(a[0]), "r"(a[1]), "r"(a[2]), "r"(a[3]), "r"(b[0]), "r"(b[1]));
}
__device__ __forceinline__ void cpasync16(uint32_t dst, const void* src) {
    asm volatile("cp.async.cg.shared.global [%0], [%1], 16;" :: "r"(dst), "l"(src));
}
__device__ __forceinline__ void cp_commit() { asm volatile("cp.async.commit_group;"); }

// ---------------------------------------------------------------------------
// gemm_h128 (R13, proven): C[M,128] = A @ B, 128 thr, 2x2 warps. For L0A.
// ---------------------------------------------------------------------------
__global__ __launch_bounds__(128)
void gemm_h128(const __half* __restrict__ Ag, const __half* __restrict__ Bg,
               __half* __restrict__ Cg, int K, int nk, int ldb,
               long sA, long sB, long sC, const float* __restrict__ bias, int relu)
{
    extern __shared__ float smp[];
    const uint32_t smb = s2u(smp);
    const int tid = threadIdx.x;
    const int lid = tid & 31;
    const int wid = tid >> 5;
    const int mw = wid >> 1;
    const int nw = wid & 1;

    const __half* Ah = Ag + blockIdx.z * sA + (size_t)blockIdx.y * 128 * K;
    const __half* Bh = Bg + blockIdx.z * sB + blockIdx.x * 128;
    __half* C = Cg + blockIdx.z * sC + (size_t)blockIdx.y * 128 * ldb + blockIdx.x * 128;
    if (bias) bias += blockIdx.x * 128;

    auto issueA = [&](int kt, int st) {
        const uint32_t dstb = smb + st * 16384;
        const __half* src = Ah + (size_t)kt * 64 + (tid & 7) * 8;
#pragma unroll
        for (int j = 0; j < 8; j++) {
            int row = (tid >> 3) + j * 16;
            cpasync16(dstb + row * 128 + (((tid & 7) ^ (row & 7)) << 4),
                      src + (size_t)row * K);
        }
    };
    auto issueB = [&](int kt, int st) {
        const uint32_t dstb = smb + 49152 + st * 16384;
#pragma unroll
        for (int j = 0; j < 8; j++) {
            int s = tid + j * 128;
            int k = s >> 4, nseg = s & 15;
            cpasync16(dstb + k * 256 + (nseg >> 3) * 128 + (((nseg & 7) ^ (k & 7)) << 4),
                      Bh + (size_t)(kt * 64 + k) * ldb + nseg * 8);
        }
    };

    int aR128[4], aR7[4];
    const int l4a = (lid >> 4) & 1;
#pragma unroll
    for (int mf = 0; mf < 4; mf++) {
        int r = mw * 64 + mf * 16 + (lid & 7) + 8 * ((lid >> 3) & 1);
        aR128[mf] = r * 128;
        aR7[mf] = r & 7;
    }
    const int t3 = (lid >> 3) & 1;
    const int kkterm = ((lid & 7) + 8 * ((lid >> 4) & 1)) * 256;
    int bOff[4];
#pragma unroll
    for (int p = 0; p < 4; p++)
        bOff[p] = nw * 128 + (((p * 2 + t3) ^ (lid & 7)) << 4);

    float acc[4][8][4];
#pragma unroll
    for (int mf = 0; mf < 4; mf++)
#pragma unroll
        for (int nf = 0; nf < 8; nf++)
#pragma unroll
            for (int e = 0; e < 4; e++) acc[mf][nf][e] = 0.f;

    issueA(0, 0); issueB(0, 0); cp_commit();
    issueA(1, 1); issueB(1, 1); cp_commit();
    asm volatile("cp.async.wait_group 1;");
    __syncthreads();

    for (int t = 0; t < nk; t++) {
        if (t + 2 < nk) {
            issueA(t + 2, (t + 2) % 3);
            issueB(t + 2, (t + 2) % 3);
            cp_commit();
        }
        const uint32_t Ab = smb + (t % 3) * 16384;
        const uint32_t Bb = smb + 49152 + (t % 3) * 16384;

        uint32_t a[2][4][4], b[2][8][2];
        auto ldfr = [&](int kb, int pb) {
#pragma unroll
            for (int mf = 0; mf < 4; mf++)
                ldsm4(a[pb][mf], Ab + aR128[mf] + ((((kb << 1) | l4a) ^ aR7[mf]) << 4));
#pragma unroll
            for (int p = 0; p < 4; p++) {
                uint32_t r[4];
                ldsm4t(r, Bb + kb * 4096 + kkterm + bOff[p]);
                b[pb][2 * p][0] = r[0];     b[pb][2 * p][1] = r[2];
                b[pb][2 * p + 1][0] = r[1]; b[pb][2 * p + 1][1] = r[3];
            }
        };

        ldfr(0, 0);
#pragma unroll
        for (int kb = 0; kb < 4; kb++) {
            if (kb < 3) ldfr(kb + 1, (kb + 1) & 1);
            const int pb = kb & 1;
#pragma unroll
            for (int mf = 0; mf < 4; mf++)
#pragma unroll
                for (int nf = 0; nf < 8; nf++)
                    mma_h(acc[mf][nf], a[pb][mf], b[pb][nf]);
        }

        if (t + 1 < nk) {
            if (t + 2 < nk) asm volatile("cp.async.wait_group 1;");
            else            asm volatile("cp.async.wait_group 0;");
            __syncthreads();
        }
    }

    const int r0 = mw * 64 + (lid >> 2);
    const int c0 = nw * 64 + (lid & 3) * 2;
#pragma unroll
    for (int mf = 0; mf < 4; mf++) {
        const int row = r0 + mf * 16;
#pragma unroll
        for (int nf = 0; nf < 8; nf++) {
            const int col = c0 + nf * 8;
            float2 v0 = make_float2(acc[mf][nf][0], acc[mf][nf][1]);
            float2 v1 = make_float2(acc[mf][nf][2], acc[mf][nf][3]);
            if (bias) {
                float bx = bias[col], by = bias[col + 1];
                v0.x += bx; v0.y += by; v1.x += bx; v1.y += by;
            }
            if (relu) {
                v0.x = fmaxf(v0.x, 0.f); v0.y = fmaxf(v0.y, 0.f);
                v1.x = fmaxf(v1.x, 0.f); v1.y = fmaxf(v1.y, 0.f);
            }
            *(uint32_t*)(C + (size_t)row * ldb + col) = pack2(v0.x, v0.y);
            *(uint32_t*)(C + (size_t)(row + 8) * ldb + col) = pack2(v1.x, v1.y);
        }
    }
}

// ---------------------------------------------------------------------------
// gemm_h256: CTA 128x256x64, 256 thr, 8 warps (2m x 4n), warp 64x64.
// One CTA covers the full N=256 -> A fetched once per m-tile; smem intensity
// 16 MAC/B. B smem rows are 512B (256 half), swizzle:
//   byte = k*512 + (nseg>>3)*128 + (((nseg&7)^(k&7))<<4), nseg = n/8 (0..31).
// FUSE_TAIL=1 (L1B): adj0-weighted column-sum epilogue -> part[b][yt][0..255].
// SMEM: A 3x16KB at 0, B 3x32KB at 49152. Total 144KB, 1 CTA/SM.
// ---------------------------------------------------------------------------
template <int FUSE_TAIL>
__global__ __launch_bounds__(256)
void gemm_h256(const __half* __restrict__ Ag, const __half* __restrict__ Bg,
               __half* __restrict__ Cg, int K, int nk,
               long sA, long sB, long sC, const float* __restrict__ bias, int relu,
               const float* __restrict__ adjw, float* __restrict__ part)
{
    extern __shared__ float smp[];
    const uint32_t smb = s2u(smp);
    const int tid = threadIdx.x;
    const int lid = tid & 31;
    const int wid = tid >> 5;
    const int mw = wid >> 2;   // 0..1
    const int nw = wid & 3;    // 0..3

    const __half* Ah = Ag + blockIdx.z * sA + (size_t)blockIdx.y * 128 * K;
    const __half* Bh = Bg + blockIdx.z * sB;
    __half* C = Cg + blockIdx.z * sC + (size_t)blockIdx.y * 128 * 256;

    auto issueA = [&](int kt, int st) {
        const uint32_t dstb = smb + st * 16384;
        const __half* src = Ah + (size_t)kt * 64 + (tid & 7) * 8;
#pragma unroll
        for (int j = 0; j < 4; j++) {
            int row = (tid >> 3) + j * 32;
            cpasync16(dstb + row * 128 + (((tid & 7) ^ (row & 7)) << 4),
                      src + (size_t)row * K);
        }
    };
    auto issueB = [&](int kt, int st) {
        const uint32_t dstb = smb + 49152 + st * 32768;
#pragma unroll
        for (int j = 0; j < 8; j++) {
            int s = tid + j * 256;
            int k = s >> 5, nseg = s & 31;
            cpasync16(dstb + k * 512 + (nseg >> 3) * 128 + (((nseg & 7) ^ (k & 7)) << 4),
                      Bh + (size_t)(kt * 64 + k) * 256 + nseg * 8);
        }
    };

    int aR128[4], aR7[4];
    const int l4a = (lid >> 4) & 1;
#pragma unroll
    for (int mf = 0; mf < 4; mf++) {
        int r = mw * 64 + mf * 16 + (lid & 7) + 8 * ((lid >> 3) & 1);
        aR128[mf] = r * 128;
        aR7[mf] = r & 7;
    }
    const int t3 = (lid >> 3) & 1;
    const int kkterm = ((lid & 7) + 8 * ((lid >> 4) & 1)) * 512;
    int bOff[4];
#pragma unroll
    for (int p = 0; p < 4; p++)
        bOff[p] = nw * 128 + (((p * 2 + t3) ^ (lid & 7)) << 4);

    float acc[4][8][4];
#pragma unroll
    for (int mf = 0; mf < 4; mf++)
#pragma unroll
        for (int nf = 0; nf < 8; nf++)
#pragma unroll
            for (int e = 0; e < 4; e++) acc[mf][nf][e] = 0.f;

    issueA(0, 0); issueB(0, 0); cp_commit();
    issueA(1, 1); issueB(1, 1); cp_commit();
    asm volatile("cp.async.wait_group 1;");
    __syncthreads();

    for (int t = 0; t < nk; t++) {
        if (t + 2 < nk) {
            issueA(t + 2, (t + 2) % 3);
            issueB(t + 2, (t + 2) % 3);
            cp_commit();
        }
        const uint32_t Ab = smb + (t % 3) * 16384;
        const uint32_t Bb = smb + 49152 + (t % 3) * 32768;

        uint32_t a[2][4][4], b[2][8][2];
        auto ldfr = [&](int kb, int pb) {
#pragma unroll
            for (int mf = 0; mf < 4; mf++)
                ldsm4(a[pb][mf], Ab + aR128[mf] + ((((kb << 1) | l4a) ^ aR7[mf]) << 4));
#pragma unroll
            for (int p = 0; p < 4; p++) {
                uint32_t r[4];
                ldsm4t(r, Bb + kb * 8192 + kkterm + bOff[p]);
                b[pb][2 * p][0] = r[0];     b[pb][2 * p][1] = r[2];
                b[pb][2 * p + 1][0] = r[1]; b[pb][2 * p + 1][1] = r[3];
            }
        };

        ldfr(0, 0);
#pragma unroll
        for (int kb = 0; kb < 4; kb++) {
            if (kb < 3) ldfr(kb + 1, (kb + 1) & 1);
            const int pb = kb & 1;
#pragma unroll
            for (int mf = 0; mf < 4; mf++)
#pragma unroll
                for (int nf = 0; nf < 8; nf++)
                    mma_h(acc[mf][nf], a[pb][mf], b[pb][nf]);
        }

        if (t + 1 < nk) {
            if (t + 2 < nk) asm volatile("cp.async.wait_group 1;");
            else            asm volatile("cp.async.wait_group 0;");
            __syncthreads();
        }
    }

    const int r0 = mw * 64 + (lid >> 2);
    const int c0 = nw * 64 + (lid & 3) * 2;

    if (!FUSE_TAIL) {
#pragma unroll
        for (int mf = 0; mf < 4; mf++) {
            const int row = r0 + mf * 16;
#pragma unroll
            for (int nf = 0; nf < 8; nf++) {
                const int col = c0 + nf * 8;
                float2 v0 = make_float2(acc[mf][nf][0], acc[mf][nf][1]);
                float2 v1 = make_float2(acc[mf][nf][2], acc[mf][nf][3]);
                if (bias) {
                    float bx = bias[col], by = bias[col + 1];
                    v0.x += bx; v0.y += by; v1.x += bx; v1.y += by;
                }
                if (relu) {
                    v0.x = fmaxf(v0.x, 0.f); v0.y = fmaxf(v0.y, 0.f);
                    v1.x = fmaxf(v1.x, 0.f); v1.y = fmaxf(v1.y, 0.f);
                }
                *(uint32_t*)(C + (size_t)row * 256 + col) = pack2(v0.x, v0.y);
                *(uint32_t*)(C + (size_t)(row + 8) * 256 + col) = pack2(v1.x, v1.y);
            }
        }
    } else {
        // fused tail: part[b][y][col] = sum_rows adj[b,0,row]*relu(acc+b1)
        const float* ar = adjw + (size_t)blockIdx.z * N_ * N_ + blockIdx.y * 128;
        float w0[4], w1[4];
#pragma unroll
        for (int mf = 0; mf < 4; mf++) {
            w0[mf] = ar[r0 + mf * 16];
            w1[mf] = ar[r0 + mf * 16 + 8];
        }
        float psum[16];
#pragma unroll
        for (int j = 0; j < 16; j++) psum[j] = 0.f;
#pragma unroll
        for (int mf = 0; mf < 4; mf++) {
#pragma unroll
            for (int nf = 0; nf < 8; nf++) {
                const int col = c0 + nf * 8;
                float bx = bias[col], by = bias[col + 1];
                float v0x = fmaxf(acc[mf][nf][0] + bx, 0.f);
                float v0y = fmaxf(acc[mf][nf][1] + by, 0.f);
                float v1x = fmaxf(acc[mf][nf][2] + bx, 0.f);
                float v1y = fmaxf(acc[mf][nf][3] + by, 0.f);
                psum[nf * 2 + 0] += w0[mf] * v0x + w1[mf] * v1x;
                psum[nf * 2 + 1] += w0[mf] * v0y + w1[mf] * v1y;
            }
        }
#pragma unroll
        for (int j = 0; j < 16; j++) {
            psum[j] += __shfl_xor_sync(0xFFFFFFFF, psum[j], 4);
            psum[j] += __shfl_xor_sync(0xFFFFFFFF, psum[j], 8);
            psum[j] += __shfl_xor_sync(0xFFFFFFFF, psum[j], 16);
        }
        float* spart = smp;  // 2 x 256 floats
        __syncthreads();
        if (lid < 4) {
#pragma unroll
            for (int nf = 0; nf < 8; nf++) {
                int cl = nw * 64 + (lid & 3) * 2 + nf * 8;
                spart[mw * 256 + cl]     = psum[nf * 2 + 0];
                spart[mw * 256 + cl + 1] = psum[nf * 2 + 1];
            }
        }
        __syncthreads();
        part[((size_t)blockIdx.z * 8 + blockIdx.y) * H_ + tid] =
            spart[tid] + spart[256 + tid];
    }
}

// ---------------- prep: all fp32 -> fp16 conversions in ONE kernel ---------
__global__ __launch_bounds__(256)
void cvt_all_kernel(const float4* __restrict__ s0, uint2* __restrict__ d0, int n0,
                    const float4* __restrict__ s1, uint2* __restrict__ d1, int n1,
                    const float4* __restrict__ s2, uint2* __restrict__ d2, int n2,
                    const float4* __restrict__ s3, uint2* __restrict__ d3, int n3)
{
    const int stride = gridDim.x * 256;
    const int t0 = blockIdx.x * 256 + threadIdx.x;
    for (int i = t0; i < n0; i += stride) {
        float4 v = s0[i];
        d0[i] = make_uint2(pack2(v.x, v.y), pack2(v.z, v.w));
    }
    for (int i = t0; i < n1; i += stride) {
        float4 v = s1[i];
        d1[i] = make_uint2(pack2(v.x, v.y), pack2(v.z, v.w));
    }
    for (int i = t0; i < n2; i += stride) {
        float4 v = s2[i];
        d2[i] = make_uint2(pack2(v.x, v.y), pack2(v.z, v.w));
    }
    for (int i = t0; i < n3; i += stride) {
        float4 v = s3[i];
        d3[i] = make_uint2(pack2(v.x, v.y), pack2(v.z, v.w));
    }
}

// ---------------- tail2: reduce part + W2(relu) + Wl head ------------------
__global__ __launch_bounds__(256)
void tail2_kernel(const float* __restrict__ part,
                  const float* __restrict__ W2, const float* __restrict__ b2,
                  const float* __restrict__ Wl, const float* __restrict__ bl,
                  float* __restrict__ out)
{
    const int b = blockIdx.x;
    const int t = threadIdx.x;
    __shared__ float rs[H_];
    __shared__ float ss[H_];

    {
        const float* p = part + b * 8 * H_ + t;
        float a = p[0];
#pragma unroll
        for (int s = 1; s < 8; s++) a += p[s * H_];
        rs[t] = a;
    }
    __syncthreads();
    {
        float a2 = b2[t];
#pragma unroll 8
        for (int k = 0; k < H_; k++)
            a2 = fmaf(rs[k], W2[k * H_ + t], a2);
        ss[t] = fmaxf(a2, 0.f);
    }
    __syncthreads();
    if (t < F_) {
        float a3 = bl[t];
#pragma unroll 8
        for (int k = 0; k < H_; k++)
            a3 = fmaf(ss[k], Wl[k * F_ + t], a3);
        out[b * F_ + t] = a3;
    }
}

extern "C" void kernel_launch(void* const* d_in, const int* in_sizes, int n_in,
                              void* d_out, int out_size)
{
    const float* embs = (const float*)d_in[0];
    const float* adj  = (const float*)d_in[1];
    const float* W0   = (const float*)d_in[2];
    const float* b0   = (const float*)d_in[3];
    const float* W1   = (const float*)d_in[4];
    const float* b1   = (const float*)d_in[5];
    const float* W2   = (const float*)d_in[6];
    const float* b2   = (const float*)d_in[7];
    const float* Wl   = (const float*)d_in[8];
    const float* bl   = (const float*)d_in[9];
    float* out = (float*)d_out;

    __half *adj16, *embs16, *W016, *W116, *T1h, *hid1h, *T2h;
    float* part;
    cudaGetSymbolAddress((void**)&adj16, g_adj16);
    cudaGetSymbolAddress((void**)&embs16, g_embs16);
    cudaGetSymbolAddress((void**)&W016, g_W016);
    cudaGetSymbolAddress((void**)&W116, g_W116);
    cudaGetSymbolAddress((void**)&T1h, g_T1h);
    cudaGetSymbolAddress((void**)&hid1h, g_hid1h);
    cudaGetSymbolAddress((void**)&T2h, g_T2h);
    cudaGetSymbolAddress((void**)&part, g_part);

    // prep: all fp32 -> fp16 (rne) in one launch
    cvt_all_kernel<<<2048, 256>>>(
        (const float4*)adj, (uint2*)adj16, (int)((size_t)B_ * N_ * N_ / 4),
        (const float4*)embs, (uint2*)embs16, B_ * N_ * F_ / 4,
        (const float4*)W0, (uint2*)W016, F_ * H_ / 4,
        (const float4*)W1, (uint2*)W116, H_ * H_ / 4);

    // L0A: T1 = adj @ embs  (N=128 kernel)
    {
        const int smem = 98304;
        cudaFuncSetAttribute(gemm_h128, cudaFuncAttributeMaxDynamicSharedMemorySize, smem);
        gemm_h128<<<dim3(1, 8, B_), 128, smem>>>(
            adj16, embs16, T1h, N_, N_ / 64, F_,
            (long)N_ * N_, (long)N_ * F_, (long)N_ * F_, nullptr, 0);
    }
    const int smem256 = 147456;
    cudaFuncSetAttribute(gemm_h256<0>, cudaFuncAttributeMaxDynamicSharedMemorySize, smem256);
    cudaFuncSetAttribute(gemm_h256<1>, cudaFuncAttributeMaxDynamicSharedMemorySize, smem256);
    // L0B: hid1 = relu(T1 @ W0 + b0)   [65536x128]@[128x256]
    gemm_h256<0><<<dim3(1, 512, 1), 256, smem256>>>(
        T1h, W016, hid1h, F_, F_ / 64, 0, 0, 0, b0, 1, nullptr, nullptr);
    // L1A: T2 = hid1 @ W1              [65536x256]@[256x256]
    gemm_h256<0><<<dim3(1, 512, 1), 256, smem256>>>(
        hid1h, W116, T2h, H_, H_ / 64, 0, 0, 0, nullptr, 0, nullptr, nullptr);
    // L1B fused with tail1: part[b][yt][col]
    gemm_h256<1><<<dim3(1, 8, B_), 256, smem256>>>(
        adj16, T2h, nullptr, N_, N_ / 64,
        (long)N_ * N_, (long)N_ * H_, 0, b1, 1, adj, part);
    // tail2
    tail2_kernel<<<B_, 256>>>(part, W2, b2, Wl, bl, out);
}

// round 16
// speedup vs baseline: 1.1499x; 1.1499x over previous
#include <cuda_runtime.h>
#include <cuda_fp16.h>
#include <cstdint>

#define B_ 64
#define N_ 1024
#define F_ 128
#define H_ 256

// Scratch (allocation-free rule: __device__ globals)
__device__ __half g_adj16[(size_t)B_ * N_ * N_];
__device__ __half g_embs16[B_ * N_ * F_];
__device__ __half g_W016[F_ * H_];
__device__ __half g_W116[H_ * H_];
__device__ __half g_hid1h[(size_t)B_ * N_ * H_];
__device__ __half g_T2h[(size_t)B_ * N_ * H_];
__device__ float g_part[B_ * 8 * H_];

__device__ __forceinline__ uint32_t s2u(const void* p) {
    uint32_t a;
    asm("{ .reg .u64 t; cvta.to.shared.u64 t, %1; cvt.u32.u64 %0, t; }" : "=r"(a) : "l"(p));
    return a;
}
__device__ __forceinline__ uint32_t pack2(float a, float b) {
    __half2 h = __floats2half2_rn(a, b);
    return *(uint32_t*)&h;
}
__device__ __forceinline__ void ldsm4(uint32_t* r, uint32_t addr) {
    asm volatile("ldmatrix.sync.aligned.m8n8.x4.shared.b16 {%0,%1,%2,%3}, [%4];"
                 : "=r"(r[0]), "=r"(r[1]), "=r"(r[2]), "=r"(r[3]) : "r"(addr));
}
__device__ __forceinline__ void ldsm4t(uint32_t* r, uint32_t addr) {
    asm volatile("ldmatrix.sync.aligned.m8n8.x4.trans.shared.b16 {%0,%1,%2,%3}, [%4];"
                 : "=r"(r[0]), "=r"(r[1]), "=r"(r[2]), "=r"(r[3]) : "r"(addr));
}
__device__ __forceinline__ void mma_h(float* d, const uint32_t* a, const uint32_t* b) {
    asm volatile(
        "mma.sync.aligned.m16n8k16.row.col.f32.f16.f16.f32 "
        "{%0,%1,%2,%3}, {%4,%5,%6,%7}, {%8,%9}, {%0,%1,%2,%3};"
        : "+f"(d[0]), "+f"(d[1]), "+f"(d[2]), "+f"(d[3])
        : "r"(a[0]), "r"(a[1]), "r"(a[2]), "r"(a[3]), "r"(b[0]), "r"(b[1]));
}
__device__ __forceinline__ void cpasync16(uint32_t dst, const void* src) {
    asm volatile("cp.async.cg.shared.global [%0], [%1], 16;" :: "r"(dst), "l"(src));
}
__device__ __forceinline__ void cp_commit() { asm volatile("cp.async.commit_group;"); }

// ---------------------------------------------------------------------------
// gemm_h (R14, proven): C = A @ B (fp16 in, f32 acc), CTA 128x128x64,
// 128 thr, 2x2 warps, warp 64x64, 3-stage dual cp.async.
// FUSE_TAIL=1: adj0-weighted column-sum epilogue -> part (hid2 never stored).
// ---------------------------------------------------------------------------
template <int FUSE_TAIL>
__global__ __launch_bounds__(128)
void gemm_h(const __half* __restrict__ Ag, const __half* __restrict__ Bg,
            __half* __restrict__ Cg, int K, int nk, int ldb,
            long sA, long sB, long sC, const float* __restrict__ bias, int relu,
            const float* __restrict__ adjw, float* __restrict__ part)
{
    extern __shared__ float smp[];
    const uint32_t smb = s2u(smp);
    const int tid = threadIdx.x;
    const int lid = tid & 31;
    const int wid = tid >> 5;
    const int mw = wid >> 1;
    const int nw = wid & 1;

    const __half* Ah = Ag + blockIdx.z * sA + (size_t)blockIdx.y * 128 * K;
    const __half* Bh = Bg + blockIdx.z * sB + blockIdx.x * 128;
    __half* C = Cg + blockIdx.z * sC + (size_t)blockIdx.y * 128 * ldb + blockIdx.x * 128;
    if (bias) bias += blockIdx.x * 128;

    auto issueA = [&](int kt, int st) {
        const uint32_t dstb = smb + st * 16384;
        const __half* src = Ah + (size_t)kt * 64 + (tid & 7) * 8;
#pragma unroll
        for (int j = 0; j < 8; j++) {
            int row = (tid >> 3) + j * 16;
            cpasync16(dstb + row * 128 + (((tid & 7) ^ (row & 7)) << 4),
                      src + (size_t)row * K);
        }
    };
    auto issueB = [&](int kt, int st) {
        const uint32_t dstb = smb + 49152 + st * 16384;
#pragma unroll
        for (int j = 0; j < 8; j++) {
            int s = tid + j * 128;
            int k = s >> 4, nseg = s & 15;
            cpasync16(dstb + k * 256 + (nseg >> 3) * 128 + (((nseg & 7) ^ (k & 7)) << 4),
                      Bh + (size_t)(kt * 64 + k) * ldb + nseg * 8);
        }
    };

    int aR128[4], aR7[4];
    const int l4a = (lid >> 4) & 1;
#pragma unroll
    for (int mf = 0; mf < 4; mf++) {
        int r = mw * 64 + mf * 16 + (lid & 7) + 8 * ((lid >> 3) & 1);
        aR128[mf] = r * 128;
        aR7[mf] = r & 7;
    }
    const int t3 = (lid >> 3) & 1;
    const int kkterm = ((lid & 7) + 8 * ((lid >> 4) & 1)) * 256;
    int bOff[4];
#pragma unroll
    for (int p = 0; p < 4; p++)
        bOff[p] = nw * 128 + (((p * 2 + t3) ^ (lid & 7)) << 4);

    float acc[4][8][4];
#pragma unroll
    for (int mf = 0; mf < 4; mf++)
#pragma unroll
        for (int nf = 0; nf < 8; nf++)
#pragma unroll
            for (int e = 0; e < 4; e++) acc[mf][nf][e] = 0.f;

    issueA(0, 0); issueB(0, 0); cp_commit();
    issueA(1, 1); issueB(1, 1); cp_commit();
    asm volatile("cp.async.wait_group 1;");
    __syncthreads();

    for (int t = 0; t < nk; t++) {
        if (t + 2 < nk) {
            issueA(t + 2, (t + 2) % 3);
            issueB(t + 2, (t + 2) % 3);
            cp_commit();
        }
        const uint32_t Ab = smb + (t % 3) * 16384;
        const uint32_t Bb = smb + 49152 + (t % 3) * 16384;

        uint32_t a[2][4][4], b[2][8][2];
        auto ldfr = [&](int kb, int pb) {
#pragma unroll
            for (int mf = 0; mf < 4; mf++)
                ldsm4(a[pb][mf], Ab + aR128[mf] + ((((kb << 1) | l4a) ^ aR7[mf]) << 4));
#pragma unroll
            for (int p = 0; p < 4; p++) {
                uint32_t r[4];
                ldsm4t(r, Bb + kb * 4096 + kkterm + bOff[p]);
                b[pb][2 * p][0] = r[0];     b[pb][2 * p][1] = r[2];
                b[pb][2 * p + 1][0] = r[1]; b[pb][2 * p + 1][1] = r[3];
            }
        };

        ldfr(0, 0);
#pragma unroll
        for (int kb = 0; kb < 4; kb++) {
            if (kb < 3) ldfr(kb + 1, (kb + 1) & 1);
            const int pb = kb & 1;
#pragma unroll
            for (int mf = 0; mf < 4; mf++)
#pragma unroll
                for (int nf = 0; nf < 8; nf++)
                    mma_h(acc[mf][nf], a[pb][mf], b[pb][nf]);
        }

        if (t + 1 < nk) {
            if (t + 2 < nk) asm volatile("cp.async.wait_group 1;");
            else            asm volatile("cp.async.wait_group 0;");
            __syncthreads();
        }
    }

    const int r0 = mw * 64 + (lid >> 2);
    const int c0 = nw * 64 + (lid & 3) * 2;

    if (!FUSE_TAIL) {
#pragma unroll
        for (int mf = 0; mf < 4; mf++) {
            const int row = r0 + mf * 16;
#pragma unroll
            for (int nf = 0; nf < 8; nf++) {
                const int col = c0 + nf * 8;
                float2 v0 = make_float2(acc[mf][nf][0], acc[mf][nf][1]);
                float2 v1 = make_float2(acc[mf][nf][2], acc[mf][nf][3]);
                if (bias) {
                    float bx = bias[col], by = bias[col + 1];
                    v0.x += bx; v0.y += by; v1.x += bx; v1.y += by;
                }
                if (relu) {
                    v0.x = fmaxf(v0.x, 0.f); v0.y = fmaxf(v0.y, 0.f);
                    v1.x = fmaxf(v1.x, 0.f); v1.y = fmaxf(v1.y, 0.f);
                }
                *(uint32_t*)(C + (size_t)row * ldb + col) = pack2(v0.x, v0.y);
                *(uint32_t*)(C + (size_t)(row + 8) * ldb + col) = pack2(v1.x, v1.y);
            }
        }
    } else {
        const float* ar = adjw + (size_t)blockIdx.z * N_ * N_ + blockIdx.y * 128;
        float w0[4], w1[4];
#pragma unroll
        for (int mf = 0; mf < 4; mf++) {
            w0[mf] = ar[r0 + mf * 16];
            w1[mf] = ar[r0 + mf * 16 + 8];
        }
        float psum[16];
#pragma unroll
        for (int j = 0; j < 16; j++) psum[j] = 0.f;
#pragma unroll
        for (int mf = 0; mf < 4; mf++) {
#pragma unroll
            for (int nf = 0; nf < 8; nf++) {
                const int col = c0 + nf * 8;
                float bx = bias[col], by = bias[col + 1];
                float v0x = fmaxf(acc[mf][nf][0] + bx, 0.f);
                float v0y = fmaxf(acc[mf][nf][1] + by, 0.f);
                float v1x = fmaxf(acc[mf][nf][2] + bx, 0.f);
                float v1y = fmaxf(acc[mf][nf][3] + by, 0.f);
                psum[nf * 2 + 0] += w0[mf] * v0x + w1[mf] * v1x;
                psum[nf * 2 + 1] += w0[mf] * v0y + w1[mf] * v1y;
            }
        }
#pragma unroll
        for (int j = 0; j < 16; j++) {
            psum[j] += __shfl_xor_sync(0xFFFFFFFF, psum[j], 4);
            psum[j] += __shfl_xor_sync(0xFFFFFFFF, psum[j], 8);
            psum[j] += __shfl_xor_sync(0xFFFFFFFF, psum[j], 16);
        }
        float* spart = smp;
        __syncthreads();
        if (lid < 4) {
#pragma unroll
            for (int nf = 0; nf < 8; nf++) {
                int cl = nw * 64 + (lid & 3) * 2 + nf * 8;
                spart[mw * 128 + cl]     = psum[nf * 2 + 0];
                spart[mw * 128 + cl + 1] = psum[nf * 2 + 1];
            }
        }
        __syncthreads();
        if (tid < 128) {
            float tot = spart[tid] + spart[128 + tid];
            part[((size_t)blockIdx.z * 8 + blockIdx.y) * H_ + blockIdx.x * 128 + tid] = tot;
        }
    }
}

// ---------------------------------------------------------------------------
// gemm_l0_fused: phase 1 computes a full 128x128 T1 tile (adj @ embs, K=1024,
// complete reduction since F=128 = one CTA's n-width). Phase 2 keeps T1 in
// SMEM (two swizzled A-tiles) and computes hid1 = relu(T1 @ W0 + b0) for the
// same 128 nodes, all 256 columns (2 n-half passes x 2 k-tiles), with W0
// staged in SMEM as two 512B-row B-tiles (R15-validated wide-B swizzle).
// Peak SMEM 96KB -> 2 CTAs/SM preserved. grid (1, 8, 64), 128 thr.
// Numerics bit-identical to separate L0A+L0B (same rounding/accum order).
// ---------------------------------------------------------------------------
__global__ __launch_bounds__(128)
void gemm_l0_fused(const __half* __restrict__ adjA, const __half* __restrict__ embsB,
                   const __half* __restrict__ W0h, const float* __restrict__ b0,
                   __half* __restrict__ hid1)
{
    extern __shared__ float smp[];
    const uint32_t smb = s2u(smp);
    const int tid = threadIdx.x;
    const int lid = tid & 31;
    const int wid = tid >> 5;
    const int mw = wid >> 1;
    const int nw = wid & 1;

    const __half* Ah = adjA + (size_t)blockIdx.z * N_ * N_ + (size_t)blockIdx.y * 128 * N_;
    const __half* Bh = embsB + (size_t)blockIdx.z * N_ * F_;

    auto issueA = [&](int kt, int st) {
        const uint32_t dstb = smb + st * 16384;
        const __half* src = Ah + (size_t)kt * 64 + (tid & 7) * 8;
#pragma unroll
        for (int j = 0; j < 8; j++) {
            int row = (tid >> 3) + j * 16;
            cpasync16(dstb + row * 128 + (((tid & 7) ^ (row & 7)) << 4),
                      src + (size_t)row * N_);
        }
    };
    auto issueB = [&](int kt, int st) {
        const uint32_t dstb = smb + 49152 + st * 16384;
#pragma unroll
        for (int j = 0; j < 8; j++) {
            int s = tid + j * 128;
            int k = s >> 4, nseg = s & 15;
            cpasync16(dstb + k * 256 + (nseg >> 3) * 128 + (((nseg & 7) ^ (k & 7)) << 4),
                      Bh + (size_t)(kt * 64 + k) * F_ + nseg * 8);
        }
    };

    int aR128[4], aR7[4];
    const int l4a = (lid >> 4) & 1;
#pragma unroll
    for (int mf = 0; mf < 4; mf++) {
        int r = mw * 64 + mf * 16 + (lid & 7) + 8 * ((lid >> 3) & 1);
        aR128[mf] = r * 128;
        aR7[mf] = r & 7;
    }
    const int t3 = (lid >> 3) & 1;
    const int kk256 = ((lid & 7) + 8 * ((lid >> 4) & 1)) * 256;
    const int kk512 = ((lid & 7) + 8 * ((lid >> 4) & 1)) * 512;
    int bOff[4];
#pragma unroll
    for (int p = 0; p < 4; p++)
        bOff[p] = nw * 128 + (((p * 2 + t3) ^ (lid & 7)) << 4);

    float acc[4][8][4];
#pragma unroll
    for (int mf = 0; mf < 4; mf++)
#pragma unroll
        for (int nf = 0; nf < 8; nf++)
#pragma unroll
            for (int e = 0; e < 4; e++) acc[mf][nf][e] = 0.f;

    // ================= phase 1: T1 tile = adj @ embs (K=1024) =================
    const int nk = N_ / 64;  // 16
    issueA(0, 0); issueB(0, 0); cp_commit();
    issueA(1, 1); issueB(1, 1); cp_commit();
    asm volatile("cp.async.wait_group 1;");
    __syncthreads();

    for (int t = 0; t < nk; t++) {
        if (t + 2 < nk) {
            issueA(t + 2, (t + 2) % 3);
            issueB(t + 2, (t + 2) % 3);
            cp_commit();
        }
        const uint32_t Ab = smb + (t % 3) * 16384;
        const uint32_t Bb = smb + 49152 + (t % 3) * 16384;

        uint32_t a[2][4][4], b[2][8][2];
        auto ldfr = [&](int kb, int pb) {
#pragma unroll
            for (int mf = 0; mf < 4; mf++)
                ldsm4(a[pb][mf], Ab + aR128[mf] + ((((kb << 1) | l4a) ^ aR7[mf]) << 4));
#pragma unroll
            for (int p = 0; p < 4; p++) {
                uint32_t r[4];
                ldsm4t(r, Bb + kb * 4096 + kk256 + bOff[p]);
                b[pb][2 * p][0] = r[0];     b[pb][2 * p][1] = r[2];
                b[pb][2 * p + 1][0] = r[1]; b[pb][2 * p + 1][1] = r[3];
            }
        };

        ldfr(0, 0);
#pragma unroll
        for (int kb = 0; kb < 4; kb++) {
            if (kb < 3) ldfr(kb + 1, (kb + 1) & 1);
            const int pb = kb & 1;
#pragma unroll
            for (int mf = 0; mf < 4; mf++)
#pragma unroll
                for (int nf = 0; nf < 8; nf++)
                    mma_h(acc[mf][nf], a[pb][mf], b[pb][nf]);
        }

        if (t + 1 < nk) {
            if (t + 2 < nk) asm volatile("cp.async.wait_group 1;");
            else            asm volatile("cp.async.wait_group 0;");
            __syncthreads();
        }
    }
    __syncthreads();  // mainloop smem reads done; safe to repurpose smem

    const int r0 = mw * 64 + (lid >> 2);
    const int c0 = nw * 64 + (lid & 3) * 2;

    // ---- write T1 (fp16 rne) into SMEM as two swizzled A-tiles at 0/16K ----
#pragma unroll
    for (int mf = 0; mf < 4; mf++) {
#pragma unroll
        for (int nf = 0; nf < 8; nf++) {
            const int col = c0 + nf * 8;
            const int tt = col >> 6, cl = col & 63;
#pragma unroll
            for (int h = 0; h < 2; h++) {
                const int row = r0 + mf * 16 + h * 8;
                uint32_t w = pack2(acc[mf][nf][2 * h + 0], acc[mf][nf][2 * h + 1]);
                *(uint32_t*)((char*)smp + tt * 16384 + row * 128 +
                             (((cl >> 3) ^ (row & 7)) << 4) + (cl & 7) * 2) = w;
            }
        }
    }

    // ---- stage all of W0 (fp16, 64KB) as two 512B-row B-tiles at 32K/64K ----
#pragma unroll
    for (int tt = 0; tt < 2; tt++) {
#pragma unroll
        for (int j = 0; j < 16; j++) {
            int s = tid + j * 128;
            int k = s >> 5, nseg = s & 31;
            cpasync16(smb + 32768 + tt * 32768 + k * 512 + (nseg >> 3) * 128 +
                          (((nseg & 7) ^ (k & 7)) << 4),
                      W0h + (size_t)(tt * 64 + k) * H_ + nseg * 8);
        }
    }
    cp_commit();
    asm volatile("cp.async.wait_group 0;");
    __syncthreads();

    // ================= phase 2: hid1 = relu(T1s @ W0s + b0) =================
    __half* hout = hid1 + ((size_t)blockIdx.z * N_ + (size_t)blockIdx.y * 128) * H_;
#pragma unroll 1
    for (int nh = 0; nh < 2; nh++) {
#pragma unroll
        for (int mf = 0; mf < 4; mf++)
#pragma unroll
            for (int nf = 0; nf < 8; nf++)
#pragma unroll
                for (int e = 0; e < 4; e++) acc[mf][nf][e] = 0.f;

#pragma unroll
        for (int t = 0; t < 2; t++) {
            const uint32_t Ab = smb + t * 16384;
            const uint32_t Bb = smb + 32768 + t * 32768;

            uint32_t a[2][4][4], b[2][8][2];
            auto ldfr2 = [&](int kb, int pb) {
#pragma unroll
                for (int mf = 0; mf < 4; mf++)
                    ldsm4(a[pb][mf], Ab + aR128[mf] + ((((kb << 1) | l4a) ^ aR7[mf]) << 4));
#pragma unroll
                for (int p = 0; p < 4; p++) {
                    uint32_t r[4];
                    ldsm4t(r, Bb + kb * 8192 + kk512 + (nh * 2 + nw) * 128 +
                               (((p * 2 + t3) ^ (lid & 7)) << 4));
                    b[pb][2 * p][0] = r[0];     b[pb][2 * p][1] = r[2];
                    b[pb][2 * p + 1][0] = r[1]; b[pb][2 * p + 1][1] = r[3];
                }
            };

            ldfr2(0, 0);
#pragma unroll
            for (int kb = 0; kb < 4; kb++) {
                if (kb < 3) ldfr2(kb + 1, (kb + 1) & 1);
                const int pb = kb & 1;
#pragma unroll
                for (int mf = 0; mf < 4; mf++)
#pragma unroll
                    for (int nf = 0; nf < 8; nf++)
                        mma_h(acc[mf][nf], a[pb][mf], b[pb][nf]);
            }
        }

        // epilogue: bias + relu, store fp16
#pragma unroll
        for (int mf = 0; mf < 4; mf++) {
            const int row = r0 + mf * 16;
#pragma unroll
            for (int nf = 0; nf < 8; nf++) {
                const int gc = nh * 128 + c0 + nf * 8;
                float bx = b0[gc], by = b0[gc + 1];
                float v0x = fmaxf(acc[mf][nf][0] + bx, 0.f);
                float v0y = fmaxf(acc[mf][nf][1] + by, 0.f);
                float v1x = fmaxf(acc[mf][nf][2] + bx, 0.f);
                float v1y = fmaxf(acc[mf][nf][3] + by, 0.f);
                *(uint32_t*)(hout + (size_t)row * H_ + gc) = pack2(v0x, v0y);
                *(uint32_t*)(hout + (size_t)(row + 8) * H_ + gc) = pack2(v1x, v1y);
            }
        }
    }
}

// ---------------- prep: all fp32 -> fp16 conversions in ONE kernel ---------
__global__ __launch_bounds__(256)
void cvt_all_kernel(const float4* __restrict__ s0, uint2* __restrict__ d0, int n0,
                    const float4* __restrict__ s1, uint2* __restrict__ d1, int n1,
                    const float4* __restrict__ s2, uint2* __restrict__ d2, int n2,
                    const float4* __restrict__ s3, uint2* __restrict__ d3, int n3)
{
    const int stride = gridDim.x * 256;
    const int t0 = blockIdx.x * 256 + threadIdx.x;
    for (int i = t0; i < n0; i += stride) {
        float4 v = s0[i];
        d0[i] = make_uint2(pack2(v.x, v.y), pack2(v.z, v.w));
    }
    for (int i = t0; i < n1; i += stride) {
        float4 v = s1[i];
        d1[i] = make_uint2(pack2(v.x, v.y), pack2(v.z, v.w));
    }
    for (int i = t0; i < n2; i += stride) {
        float4 v = s2[i];
        d2[i] = make_uint2(pack2(v.x, v.y), pack2(v.z, v.w));
    }
    for (int i = t0; i < n3; i += stride) {
        float4 v = s3[i];
        d3[i] = make_uint2(pack2(v.x, v.y), pack2(v.z, v.w));
    }
}

// ---------------- tail2: reduce part + W2(relu) + Wl head ------------------
__global__ __launch_bounds__(256)
void tail2_kernel(const float* __restrict__ part,
                  const float* __restrict__ W2, const float* __restrict__ b2,
                  const float* __restrict__ Wl, const float* __restrict__ bl,
                  float* __restrict__ out)
{
    const int b = blockIdx.x;
    const int t = threadIdx.x;
    __shared__ float rs[H_];
    __shared__ float ss[H_];

    {
        const float* p = part + b * 8 * H_ + t;
        float a = p[0];
#pragma unroll
        for (int s = 1; s < 8; s++) a += p[s * H_];
        rs[t] = a;
    }
    __syncthreads();
    {
        float a2 = b2[t];
#pragma unroll 8
        for (int k = 0; k < H_; k++)
            a2 = fmaf(rs[k], W2[k * H_ + t], a2);
        ss[t] = fmaxf(a2, 0.f);
    }
    __syncthreads();
    if (t < F_) {
        float a3 = bl[t];
#pragma unroll 8
        for (int k = 0; k < H_; k++)
            a3 = fmaf(ss[k], Wl[k * F_ + t], a3);
        out[b * F_ + t] = a3;
    }
}

extern "C" void kernel_launch(void* const* d_in, const int* in_sizes, int n_in,
                              void* d_out, int out_size)
{
    const float* embs = (const float*)d_in[0];
    const float* adj  = (const float*)d_in[1];
    const float* W0   = (const float*)d_in[2];
    const float* b0   = (const float*)d_in[3];
    const float* W1   = (const float*)d_in[4];
    const float* b1   = (const float*)d_in[5];
    const float* W2   = (const float*)d_in[6];
    const float* b2   = (const float*)d_in[7];
    const float* Wl   = (const float*)d_in[8];
    const float* bl   = (const float*)d_in[9];
    float* out = (float*)d_out;

    __half *adj16, *embs16, *W016, *W116, *hid1h, *T2h;
    float* part;
    cudaGetSymbolAddress((void**)&adj16, g_adj16);
    cudaGetSymbolAddress((void**)&embs16, g_embs16);
    cudaGetSymbolAddress((void**)&W016, g_W016);
    cudaGetSymbolAddress((void**)&W116, g_W116);
    cudaGetSymbolAddress((void**)&hid1h, g_hid1h);
    cudaGetSymbolAddress((void**)&T2h, g_T2h);
    cudaGetSymbolAddress((void**)&part, g_part);

    // prep: all fp32 -> fp16 (rne) in one launch
    cvt_all_kernel<<<2048, 256>>>(
        (const float4*)adj, (uint2*)adj16, (int)((size_t)B_ * N_ * N_ / 4),
        (const float4*)embs, (uint2*)embs16, B_ * N_ * F_ / 4,
        (const float4*)W0, (uint2*)W016, F_ * H_ / 4,
        (const float4*)W1, (uint2*)W116, H_ * H_ / 4);

    const int smem = 98304;
    cudaFuncSetAttribute(gemm_l0_fused, cudaFuncAttributeMaxDynamicSharedMemorySize, smem);
    cudaFuncSetAttribute(gemm_h<0>, cudaFuncAttributeMaxDynamicSharedMemorySize, smem);
    cudaFuncSetAttribute(gemm_h<1>, cudaFuncAttributeMaxDynamicSharedMemorySize, smem);

    // L0 fused: hid1 = relu((adj @ embs) @ W0 + b0), T1 never leaves SMEM
    gemm_l0_fused<<<dim3(1, 8, B_), 128, smem>>>(adj16, embs16, W016, b0, hid1h);
    // L1A: T2 = hid1 @ W1  [65536x256]@[256x256]
    gemm_h<0><<<dim3(2, 512, 1), 128, smem>>>(
        hid1h, W116, T2h, H_, H_ / 64, H_, 0, 0, 0, nullptr, 0, nullptr, nullptr);
    // L1B fused with tail1: part[b][yt][col]
    gemm_h<1><<<dim3(2, 8, B_), 128, smem>>>(
        adj16, T2h, nullptr, N_, N_ / 64, H_,
        (long)N_ * N_, (long)N_ * H_, 0, b1, 1, adj, part);
    // tail2
    tail2_kernel<<<B_, 256>>>(part, W2, b2, Wl, bl, out);
}